// round 2
// baseline (speedup 1.0000x reference)
#include <cuda_runtime.h>

// FilterLayer: y[b,c,h,w] = sum_{i,j in 5x5} x_pad[b,c,h+i,w+j] * f[b,i*5+j,h,w]
// Shapes fixed by the problem: x [4,3,512,512] f32, f [4,25,512,512] f32, out [4,3,512,512] f32.

#define Hc 512
#define Wc 512
#define Bc 4
#define Cc 3
#define WIN 5
#define NK (WIN * WIN)
#define PAD (WIN / 2)

#define TILE_W 128            // output pixels per block in w (32 threads x 4 px)
#define TILE_H 8              // output rows per block
#define TW (TILE_W + 2 * PAD) // 132 (multiple of 4 -> rows stay 16B aligned)
#define TH (TILE_H + 2 * PAD) // 12

__global__ __launch_bounds__(256, 2)
void filter5x5_kernel(const float* __restrict__ x,
                      const float* __restrict__ f,
                      float* __restrict__ out)
{
    __shared__ float xs[Cc][TH][TW]; // 3*12*132*4 = 19008 B

    const int tx  = threadIdx.x;           // 0..31
    const int ty  = threadIdx.y;           // 0..7
    const int tid = ty * 32 + tx;
    const int b   = blockIdx.z;
    const int h0  = blockIdx.y * TILE_H;
    const int w0  = blockIdx.x * TILE_W;

    // ---- cooperative load of x halo tile (3 x 12 x 132 floats) ----
    #pragma unroll 1
    for (int idx = tid; idx < Cc * TH * TW; idx += 256) {
        const int c   = idx / (TH * TW);
        const int rem = idx - c * (TH * TW);
        const int r   = rem / TW;
        const int cc  = rem - r * TW;
        const int gh  = h0 + r - PAD;
        const int gw  = w0 + cc - PAD;
        float v = 0.0f;
        if (gh >= 0 && gh < Hc && gw >= 0 && gw < Wc)
            v = x[((b * Cc + c) * Hc + gh) * Wc + gw];
        xs[c][r][cc] = v;
    }
    __syncthreads();

    // ---- per-thread accumulation: 4 w-pixels x 3 channels ----
    float acc[Cc][4];
    #pragma unroll
    for (int c = 0; c < Cc; c++)
        #pragma unroll
        for (int p = 0; p < 4; p++)
            acc[c][p] = 0.0f;

    const int h = h0 + ty;
    const int w = w0 + tx * 4;

    // f is [B, 25, H, W]; this thread reads float4 at (b, k, h, w)
    const float4* f4 = reinterpret_cast<const float4*>(
        f + ((b * NK) * Hc + h) * Wc + w);
    const int kstride4 = (Hc * Wc) / 4; // float4 stride between taps

    #pragma unroll
    for (int i = 0; i < WIN; i++) {
        // Load the 8 needed x values per channel for this tap-row via two
        // aligned, conflict-free LDS.128s.
        float xr[Cc][8];
        #pragma unroll
        for (int c = 0; c < Cc; c++) {
            const float4* row = reinterpret_cast<const float4*>(&xs[c][ty + i][0]);
            const float4 a = row[tx];
            const float4 bq = row[tx + 1];
            xr[c][0] = a.x;  xr[c][1] = a.y;  xr[c][2] = a.z;  xr[c][3] = a.w;
            xr[c][4] = bq.x; xr[c][5] = bq.y; xr[c][6] = bq.z; xr[c][7] = bq.w;
        }
        #pragma unroll
        for (int j = 0; j < WIN; j++) {
            const int k = i * WIN + j;
            const float4 fk = f4[k * kstride4];
            #pragma unroll
            for (int c = 0; c < Cc; c++) {
                acc[c][0] = fmaf(fk.x, xr[c][j + 0], acc[c][0]);
                acc[c][1] = fmaf(fk.y, xr[c][j + 1], acc[c][1]);
                acc[c][2] = fmaf(fk.z, xr[c][j + 2], acc[c][2]);
                acc[c][3] = fmaf(fk.w, xr[c][j + 3], acc[c][3]);
            }
        }
    }

    // ---- vectorized stores ----
    #pragma unroll
    for (int c = 0; c < Cc; c++) {
        float4 o = make_float4(acc[c][0], acc[c][1], acc[c][2], acc[c][3]);
        *reinterpret_cast<float4*>(out + ((b * Cc + c) * Hc + h) * Wc + w) = o;
    }
}

extern "C" void kernel_launch(void* const* d_in, const int* in_sizes, int n_in,
                              void* d_out, int out_size)
{
    const float* x = (const float*)d_in[0]; // [4,3,512,512]
    const float* f = (const float*)d_in[1]; // [4,25,512,512]
    float* out = (float*)d_out;             // [4,3,512,512]
    (void)in_sizes; (void)n_in; (void)out_size;

    dim3 block(32, 8, 1);
    dim3 grid(Wc / TILE_W, Hc / TILE_H, Bc); // (4, 64, 4) = 1024 blocks
    filter5x5_kernel<<<grid, block>>>(x, f, out);
}

// round 3
// speedup vs baseline: 1.2229x; 1.2229x over previous
#include <cuda_runtime.h>

// FilterLayer: y[b,c,h,w] = sum_{i,j in 5x5} x_pad[b,c,h+i,w+j] * f[b,i*5+j,h,w]
// x [4,3,512,512] f32, f [4,25,512,512] f32, out [4,3,512,512] f32.

#define Hc 512
#define Wc 512
#define Bc 4
#define Cc 3
#define WIN 5
#define NK (WIN * WIN)
#define PAD (WIN / 2)

#define TILE_W 128            // 32 threads x 4 px
#define TILE_H 8
#define TW (TILE_W + 2 * PAD) // 132 floats per row (16B-aligned rows)
#define TH (TILE_H + 2 * PAD) // 12

__global__ __launch_bounds__(256, 3)
void filter5x5_kernel(const float* __restrict__ x,
                      const float* __restrict__ f,
                      float* __restrict__ out)
{
    __shared__ float xs[Cc][TH][TW]; // 19008 B

    const int tx  = threadIdx.x;      // 0..31
    const int ty  = threadIdx.y;      // 0..7
    const int tid = ty * 32 + tx;
    const int b   = blockIdx.z;
    const int h0  = blockIdx.y * TILE_H;
    const int w0  = blockIdx.x * TILE_W;

    // ---- cooperative x halo load (3 x 12 x 132) ----
    #pragma unroll 1
    for (int idx = tid; idx < Cc * TH * TW; idx += 256) {
        const int c   = idx / (TH * TW);
        const int rem = idx - c * (TH * TW);
        const int r   = rem / TW;
        const int cc  = rem - r * TW;
        const int gh  = h0 + r - PAD;
        const int gw  = w0 + cc - PAD;
        float v = 0.0f;
        if (gh >= 0 && gh < Hc && gw >= 0 && gw < Wc)
            v = x[((b * Cc + c) * Hc + gh) * Wc + gw];
        xs[c][r][cc] = v;
    }
    __syncthreads();

    float acc[Cc][4];
    #pragma unroll
    for (int c = 0; c < Cc; c++)
        #pragma unroll
        for (int p = 0; p < 4; p++)
            acc[c][p] = 0.0f;

    const int h = h0 + ty;
    const int w = w0 + tx * 4;

    const float4* f4 = reinterpret_cast<const float4*>(
        f + ((b * NK) * Hc + h) * Wc + w);
    const int kstride4 = (Hc * Wc) / 4;

    #pragma unroll
    for (int i = 0; i < WIN; i++) {
        // Burst-issue the 5 independent f loads for this tap row (MLP=5).
        float4 fk[WIN];
        #pragma unroll
        for (int j = 0; j < WIN; j++)
            fk[j] = f4[(i * WIN + j) * kstride4];

        // Channels sequential: only 8 x-values live at a time.
        #pragma unroll
        for (int c = 0; c < Cc; c++) {
            const float4* row = reinterpret_cast<const float4*>(&xs[c][ty + i][0]);
            const float4 a  = row[tx];
            const float4 bq = row[tx + 1];
            float xr[8];
            xr[0] = a.x;  xr[1] = a.y;  xr[2] = a.z;  xr[3] = a.w;
            xr[4] = bq.x; xr[5] = bq.y; xr[6] = bq.z; xr[7] = bq.w;

            #pragma unroll
            for (int j = 0; j < WIN; j++) {
                acc[c][0] = fmaf(fk[j].x, xr[j + 0], acc[c][0]);
                acc[c][1] = fmaf(fk[j].y, xr[j + 1], acc[c][1]);
                acc[c][2] = fmaf(fk[j].z, xr[j + 2], acc[c][2]);
                acc[c][3] = fmaf(fk[j].w, xr[j + 3], acc[c][3]);
            }
        }
    }

    #pragma unroll
    for (int c = 0; c < Cc; c++) {
        float4 o = make_float4(acc[c][0], acc[c][1], acc[c][2], acc[c][3]);
        *reinterpret_cast<float4*>(out + ((b * Cc + c) * Hc + h) * Wc + w) = o;
    }
}

extern "C" void kernel_launch(void* const* d_in, const int* in_sizes, int n_in,
                              void* d_out, int out_size)
{
    const float* x = (const float*)d_in[0];
    const float* f = (const float*)d_in[1];
    float* out = (float*)d_out;
    (void)in_sizes; (void)n_in; (void)out_size;

    dim3 block(32, 8, 1);
    dim3 grid(Wc / TILE_W, Hc / TILE_H, Bc); // (4, 64, 4)
    filter5x5_kernel<<<grid, block>>>(x, f, out);
}